// round 7
// baseline (speedup 1.0000x reference)
#include <cuda_runtime.h>
#include <cuda_fp16.h>
#include <math.h>
#include <stdint.h>

#define B_ROWS 1024
#define M_TOT  200000
#define D_INP  256
#define DIM    128
#define D_OUT  10
#define M_PAD  200192            /* 1564*128 */
#define N_MT   1564              /* m-tiles of 128 */
#define NBLK   782               /* histogram blocks of 256 */
#define MAX_CTAS 512

// ---------------------------------------------------------------- helpers
__device__ __forceinline__ uint32_t smem_to_u32(const void* p) {
    uint32_t a;
    asm("{ .reg .u64 t; cvta.to.shared.u64 t, %1; cvt.u32.u64 %0, t; }"
        : "=r"(a) : "l"(p));
    return a;
}
__device__ __forceinline__ void ldsm4(uint32_t r[4], uint32_t addr) {
    asm volatile("ldmatrix.sync.aligned.m8n8.x4.shared.b16 {%0,%1,%2,%3}, [%4];"
                 : "=r"(r[0]), "=r"(r[1]), "=r"(r[2]), "=r"(r[3]) : "r"(addr));
}
__device__ __forceinline__ void mma16816(float c[4], const uint32_t a[4],
                                         const uint32_t b0, const uint32_t b1) {
    asm volatile("mma.sync.aligned.m16n8k16.row.col.f32.f16.f16.f32 "
                 "{%0,%1,%2,%3}, {%4,%5,%6,%7}, {%8,%9}, {%0,%1,%2,%3};"
                 : "+f"(c[0]), "+f"(c[1]), "+f"(c[2]), "+f"(c[3])
                 : "r"(a[0]), "r"(a[1]), "r"(a[2]), "r"(a[3]), "r"(b0), "r"(b1));
}
// fp16-accumulate variant: D/C are 2 b32 regs (4 halves)
__device__ __forceinline__ void mma16816h(uint32_t c[2], const uint32_t a[4],
                                          const uint32_t b0, const uint32_t b1) {
    asm volatile("mma.sync.aligned.m16n8k16.row.col.f16.f16.f16.f16 "
                 "{%0,%1}, {%2,%3,%4,%5}, {%6,%7}, {%0,%1};"
                 : "+r"(c[0]), "+r"(c[1])
                 : "r"(a[0]), "r"(a[1]), "r"(a[2]), "r"(a[3]), "r"(b0), "r"(b1));
}
__device__ __forceinline__ float sqrt_approx(float x) {
    float r; asm("sqrt.approx.f32 %0, %1;" : "=f"(r) : "f"(x)); return r;
}
__device__ __forceinline__ void cp_async16(uint32_t dst, const void* src) {
    asm volatile("cp.async.ca.shared.global [%0], [%1], 16;"
                 :: "r"(dst), "l"(src) : "memory");
}
__device__ __forceinline__ void cp_commit() {
    asm volatile("cp.async.commit_group;" ::: "memory");
}
__device__ __forceinline__ void cp_wait0() {
    asm volatile("cp.async.wait_group 0;" ::: "memory");
}
// A-fragment ldmatrix (16 rows x 16 k)
__device__ __forceinline__ void lda_frag(uint32_t a[4], uint32_t base, int R0,
                                         int ks, int lane, int rstride) {
    int row = R0 + (lane & 15);
    int kb  = ks * 32 + ((lane >> 4) << 4);
    ldsm4(a, base + row * rstride + (kb ^ ((row & 7) << 4)));
}
// B-fragment ldmatrix: two n-tiles of 8
__device__ __forceinline__ void ldb_frag(uint32_t b[4], uint32_t base, int N0,
                                         int ks, int lane, int rstride) {
    int row = N0 + (lane & 7) + ((lane >> 4) << 3);
    int kb  = ks * 32 + ((lane >> 3) & 1) * 16;
    ldsm4(b, base + row * rstride + (kb ^ ((row & 7) << 4)));
}

// ---------------------------------------------------------------- scratch
__device__ __half g_h   [B_ROWS * DIM];
__device__ float  g_hn2 [B_ROWS];
__device__ __half g_hc  [(size_t)M_PAD * DIM];
__device__ float  g_hcn2[M_PAD];
__device__ int    g_src [M_PAD];
__device__ int    g_cls [M_PAD];
__device__ int    g_bh  [NBLK * D_OUT];
__device__ int    g_boff[NBLK * D_OUT];
__device__ int    g_coff[D_OUT];
__device__ float  g_part[(size_t)MAX_CTAS * B_ROWS * D_OUT];

// ---------------------------------------------------------------- sort
__global__ void k_hist(const int* __restrict__ cy) {
    __shared__ int cnt[D_OUT];
    int t = threadIdx.x, b = blockIdx.x;
    if (t < D_OUT) cnt[t] = 0;
    __syncthreads();
    int m = b * 256 + t;
    if (m < M_TOT) atomicAdd(&cnt[cy[m]], 1);
    __syncthreads();
    if (t < D_OUT) g_bh[b * D_OUT + t] = cnt[t];
}
__global__ void k_scan() {
    __shared__ int tot[D_OUT];
    int t = threadIdx.x;
    if (t < D_OUT) {
        int run = 0;
        for (int b = 0; b < NBLK; b++) {
            int v = g_bh[b * D_OUT + t];
            g_boff[b * D_OUT + t] = run;
            run += v;
        }
        tot[t] = run;
    }
    __syncthreads();
    if (t == 0) {
        int off = 0;
        for (int c = 0; c < D_OUT; c++) { g_coff[c] = off; off += tot[c]; }
        for (int p = M_TOT; p < M_PAD; p++) g_cls[p] = D_OUT - 1;
    }
}
__global__ void k_rank(const int* __restrict__ cy) {
    __shared__ int cls[256];
    int t = threadIdx.x, b = blockIdx.x;
    int m = b * 256 + t;
    int c = (m < M_TOT) ? cy[m] : -1;
    cls[t] = c;
    __syncthreads();
    if (m < M_TOT) {
        int r = 0;
        for (int j = 0; j < t; j++) r += (cls[j] == c);
        int pos = g_coff[c] + g_boff[b * D_OUT + c] + r;
        g_src[pos] = m;
        g_cls[pos] = c;
    }
}

// ---------------------------------------------------------------- projection GEMMs
#define HC_A 0
#define HC_B 65536
#define HC_BIAS 131072
#define HC_SRC  131584
#define HC_PART 132096
#define SMEM_HC_BYTES (HC_PART + 1024)

template <bool GATHER>
__device__ __forceinline__ void proj_body(const float* __restrict__ src_mat,
                                          const float* __restrict__ W,
                                          __half* __restrict__ out_h,
                                          float* __restrict__ out_n2,
                                          int tile, bool pad_check) {
    extern __shared__ char smem[];
    uint32_t sb = smem_to_u32(smem);
    float* bias_s = (float*)(smem + HC_BIAS);
    int*   srcs   = (int*)(smem + HC_SRC);
    float* part   = (float*)(smem + HC_PART);
    int tid = threadIdx.x, lane = tid & 31, wid = tid >> 5;
    int wr = wid & 7, wc = wid >> 3;

    __syncthreads();   // srcs/bias ready (caller filled)

#pragma unroll
    for (int i = 0; i < 8; i++) {
        int idx = tid + i * 512;
        int r = idx >> 5, kb = (idx & 31) * 16;
        size_t srow = GATHER ? (size_t)srcs[r] : ((size_t)tile * 128 + r);
        const float4* s4 = (const float4*)(src_mat + srow * D_INP + kb / 2);
        float4 v0 = s4[0], v1 = s4[1];
        __half2 h0 = __floats2half2_rn(v0.x, v0.y), h1 = __floats2half2_rn(v0.z, v0.w);
        __half2 h2 = __floats2half2_rn(v1.x, v1.y), h3 = __floats2half2_rn(v1.z, v1.w);
        *(uint4*)(smem + HC_A + r * 512 + (kb ^ ((r & 7) << 4))) =
            make_uint4(*(uint32_t*)&h0, *(uint32_t*)&h1, *(uint32_t*)&h2, *(uint32_t*)&h3);
    }
#pragma unroll
    for (int i = 0; i < 8; i++) {
        int idx = tid + i * 512;
        int r = idx >> 5, kb = (idx & 31) * 16;
        const float4* s4 = (const float4*)(W + (size_t)r * D_INP + kb / 2);
        float4 v0 = s4[0], v1 = s4[1];
        __half2 h0 = __floats2half2_rn(v0.x, v0.y), h1 = __floats2half2_rn(v0.z, v0.w);
        __half2 h2 = __floats2half2_rn(v1.x, v1.y), h3 = __floats2half2_rn(v1.z, v1.w);
        *(uint4*)(smem + HC_B + r * 512 + (kb ^ ((r & 7) << 4))) =
            make_uint4(*(uint32_t*)&h0, *(uint32_t*)&h1, *(uint32_t*)&h2, *(uint32_t*)&h3);
    }
    __syncthreads();

    float acc[8][4];
#pragma unroll
    for (int n = 0; n < 8; n++)
#pragma unroll
        for (int j = 0; j < 4; j++) acc[n][j] = 0.f;
#pragma unroll
    for (int ks = 0; ks < 16; ks++) {
        uint32_t a[4], bf[4][4];
        lda_frag(a, sb + HC_A, wr * 16, ks, lane, 512);
#pragma unroll
        for (int p = 0; p < 4; p++)
            ldb_frag(bf[p], sb + HC_B, wc * 64 + p * 16, ks, lane, 512);
#pragma unroll
        for (int nt = 0; nt < 8; nt++)
            mma16816(acc[nt], a, bf[nt >> 1][(nt & 1) * 2], bf[nt >> 1][(nt & 1) * 2 + 1]);
    }

    float sumsq[2] = {0.f, 0.f};
#pragma unroll
    for (int hr = 0; hr < 2; hr++) {
        int row = wr * 16 + (lane >> 2) + hr * 8;
        size_t gm = (size_t)tile * 128 + row;
#pragma unroll
        for (int nt = 0; nt < 8; nt++) {
            int d0 = wc * 64 + nt * 8 + (lane & 3) * 2;
            float v0 = acc[nt][hr * 2 + 0] + bias_s[d0];
            float v1 = acc[nt][hr * 2 + 1] + bias_s[d0 + 1];
            __half2 hp = __floats2half2_rn(v0, v1);
            float2 vr = __half22float2(hp);
            sumsq[hr] = fmaf(vr.x, vr.x, sumsq[hr]);
            sumsq[hr] = fmaf(vr.y, vr.y, sumsq[hr]);
            *(__half2*)(out_h + gm * DIM + d0) = hp;
        }
    }
#pragma unroll
    for (int hr = 0; hr < 2; hr++) {
        float v = sumsq[hr];
        v += __shfl_xor_sync(0xFFFFFFFF, v, 1);
        v += __shfl_xor_sync(0xFFFFFFFF, v, 2);
        if ((lane & 3) == 0) {
            int row = wr * 16 + (lane >> 2) + hr * 8;
            part[row * 2 + wc] = v;
        }
    }
    __syncthreads();
    if (tid < 128) {
        size_t gm = (size_t)tile * 128 + tid;
        float v = part[tid * 2] + part[tid * 2 + 1];
        out_n2[gm] = (!pad_check || gm < M_TOT) ? v : 3e38f;
    }
}

__global__ __launch_bounds__(512, 1) void k_hq(const float* __restrict__ x,
                                               const float* __restrict__ W,
                                               const float* __restrict__ be) {
    extern __shared__ char smem[];
    float* bias_s = (float*)(smem + HC_BIAS);
    if (threadIdx.x < 128) bias_s[threadIdx.x] = be[threadIdx.x];
    proj_body<false>(x, W, g_h, g_hn2, blockIdx.x, false);
}

__global__ __launch_bounds__(512, 1) void k_hc(const float* __restrict__ cx,
                                               const float* __restrict__ W,
                                               const float* __restrict__ be) {
    extern __shared__ char smem[];
    float* bias_s = (float*)(smem + HC_BIAS);
    int*   srcs   = (int*)(smem + HC_SRC);
    int tid = threadIdx.x;
    if (tid < 128) {
        int p = blockIdx.x * 128 + tid;
        srcs[tid]   = (p < M_TOT) ? g_src[p] : 0;
        bias_s[tid] = be[tid];
    }
    proj_body<true>(cx, W, g_hc, g_hcn2, blockIdx.x, true);
}

// ---------------------------------------------------------------- k_main
// 512 threads / 16 warps: wr=wid&7 (16-row strip of 128 B-rows), wc=wid>>3
#define KM_A0 0
#define KM_A1 32768
#define KM_B  65536
#define KM_SS 98304
#define SMEM_MAIN_BYTES (KM_SS + 2 * B_ROWS * D_OUT * 4)

__device__ __forceinline__ void cp_a_chunk(uint32_t sdst, int chunk, int tid) {
#pragma unroll
    for (int i = 0; i < 4; i++) {
        int idx = tid + i * 512;
        int r = idx >> 4, kb = (idx & 15) * 16;
        cp_async16(sdst + r * 256 + (kb ^ ((r & 7) << 4)),
                   (const char*)g_h + ((size_t)chunk * 128 + r) * 256 + kb);
    }
    cp_commit();
}

// fp16-accum MMA over one 128x128x128 chunk
__device__ __forceinline__ void mma_chunk_h(uint32_t (&acc)[8][2], uint32_t abase,
                                            uint32_t bbase, int wr, int wc, int lane) {
#pragma unroll
    for (int n = 0; n < 8; n++) { acc[n][0] = 0u; acc[n][1] = 0u; }
#pragma unroll
    for (int ks = 0; ks < 8; ks++) {
        uint32_t a[4], bf[4][4];
        lda_frag(a, abase, wr * 16, ks, lane, 256);
#pragma unroll
        for (int p = 0; p < 4; p++)
            ldb_frag(bf[p], bbase, wc * 64 + p * 16, ks, lane, 256);
#pragma unroll
        for (int nt = 0; nt < 8; nt++)
            mma16816h(acc[nt], a, bf[nt >> 1][(nt & 1) * 2], bf[nt >> 1][(nt & 1) * 2 + 1]);
    }
}

__device__ __forceinline__ void epi_reduce_store(float (&rs)[2], float* s_s,
                                                 int cprev, int cls,
                                                 int wr, int wc, int lane) {
#pragma unroll
    for (int hr = 0; hr < 2; hr++) {
        float v = rs[hr];
        v += __shfl_xor_sync(0xFFFFFFFF, v, 1);
        v += __shfl_xor_sync(0xFFFFFFFF, v, 2);
        if ((lane & 3) == 0) {
            int brow = cprev * 128 + wr * 16 + (lane >> 2) + hr * 8;
            s_s[wc * (B_ROWS * D_OUT) + brow * D_OUT + cls] += v;
        }
    }
}

// epilogue of one slice (nt) of a chunk: 4 elements from packed half accums
__device__ __forceinline__ void epi_slice(const uint32_t (&accP)[2], float hn0, float hn1,
                                          const float* cn2, float (&rs)[2]) {
    float2 f01 = __half22float2(*(const __half2*)&accP[0]);  // row r
    float2 f23 = __half22float2(*(const __half2*)&accP[1]);  // row r+8
    float sq0 = fmaf(-2.f, f01.x, hn0 + cn2[0]);
    float sq1 = fmaf(-2.f, f01.y, hn0 + cn2[1]);
    float sq2 = fmaf(-2.f, f23.x, hn1 + cn2[0]);
    float sq3 = fmaf(-2.f, f23.y, hn1 + cn2[1]);
    sq0 = fmaxf(sq0, 1e-30f); sq1 = fmaxf(sq1, 1e-30f);
    sq2 = fmaxf(sq2, 1e-30f); sq3 = fmaxf(sq3, 1e-30f);
    rs[0] += __expf(-sqrt_approx(sq0)) + __expf(-sqrt_approx(sq1));
    rs[1] += __expf(-sqrt_approx(sq2)) + __expf(-sqrt_approx(sq3));
}

// MMA of chunk c interleaved with epilogue of chunk c-1 (pure-class tile)
__device__ __forceinline__ void mma_chunk_epi(uint32_t (&accN)[8][2],
                                              const uint32_t (&accP)[8][2],
                                              uint32_t abase, uint32_t bbase,
                                              const float (&cn16)[16], float* s_s,
                                              int cprev, int cls,
                                              int wr, int wc, int lane) {
    int r0 = cprev * 128 + wr * 16 + (lane >> 2);
    float hn0 = g_hn2[r0], hn1 = g_hn2[r0 + 8];
    float rs[2] = {0.f, 0.f};
#pragma unroll
    for (int n = 0; n < 8; n++) { accN[n][0] = 0u; accN[n][1] = 0u; }
#pragma unroll
    for (int ks = 0; ks < 8; ks++) {
        uint32_t a[4], bf[4][4];
        lda_frag(a, abase, wr * 16, ks, lane, 256);
#pragma unroll
        for (int p = 0; p < 4; p++)
            ldb_frag(bf[p], bbase, wc * 64 + p * 16, ks, lane, 256);
#pragma unroll
        for (int nt = 0; nt < 8; nt++)
            mma16816h(accN[nt], a, bf[nt >> 1][(nt & 1) * 2], bf[nt >> 1][(nt & 1) * 2 + 1]);
        epi_slice(accP[ks], hn0, hn1, &cn16[ks * 2], rs);
    }
    epi_reduce_store(rs, s_s, cprev, cls, wr, wc, lane);
}

__device__ __forceinline__ void epi_only(const uint32_t (&accP)[8][2],
                                         const float (&cn16)[16], float* s_s,
                                         int cprev, int cls,
                                         int wr, int wc, int lane) {
    int r0 = cprev * 128 + wr * 16 + (lane >> 2);
    float hn0 = g_hn2[r0], hn1 = g_hn2[r0 + 8];
    float rs[2] = {0.f, 0.f};
#pragma unroll
    for (int nt = 0; nt < 8; nt++)
        epi_slice(accP[nt], hn0, hn1, &cn16[nt * 2], rs);
    epi_reduce_store(rs, s_s, cprev, cls, wr, wc, lane);
}

__global__ __launch_bounds__(512, 1) void k_main() {
    extern __shared__ char smem[];
    uint32_t sb = smem_to_u32(smem);
    float* s_s = (float*)(smem + KM_SS);
    int tid = threadIdx.x, lane = tid & 31, wid = tid >> 5;
    int wr = wid & 7, wc = wid >> 3;
    uint32_t AB[2] = {sb + KM_A0, sb + KM_A1};
    uint32_t BB = sb + KM_B;

    for (int i = tid; i < 2 * B_ROWS * D_OUT; i += 512) s_s[i] = 0.f;

    uint32_t acc[2][8][2];

    for (int mt = blockIdx.x; mt < N_MT; mt += gridDim.x) {
        __syncthreads();   // prior mt fully done before B/A overwrite
        // B tile (hc rows mt*128..+128) via cp.async
#pragma unroll
        for (int i = 0; i < 4; i++) {
            int idx = tid + i * 512;
            int r = idx >> 4, kb = (idx & 15) * 16;
            cp_async16(BB + r * 256 + (kb ^ ((r & 7) << 4)),
                       (const char*)g_hc + ((size_t)mt * 128 + r) * 256 + kb);
        }
        cp_a_chunk(AB[0], 0, tid);
        int mbase = mt * 128;
        float cn16[16];
#pragma unroll
        for (int nt = 0; nt < 8; nt++) {
            int m0 = mbase + wc * 64 + nt * 8 + (lane & 3) * 2;
            cn16[nt * 2]     = g_hcn2[m0];
            cn16[nt * 2 + 1] = g_hcn2[m0 + 1];
        }
        int c_lo = g_cls[mbase], c_hi = g_cls[mbase + 127];
        cp_wait0();
        __syncthreads();

        if (c_lo == c_hi) {
            // chunk 0: prefetch chunk1, mma chunk0 (no previous epilogue)
            cp_a_chunk(AB[1], 1, tid);
            mma_chunk_h(acc[0], AB[0], BB, wr, wc, lane);
            cp_wait0();
            __syncthreads();
#pragma unroll 1
            for (int c = 1; c < 8; c++) {
                if (c < 7) cp_a_chunk(AB[(c + 1) & 1], c + 1, tid);
                mma_chunk_epi(acc[c & 1], acc[(c - 1) & 1], AB[c & 1], BB,
                              cn16, s_s, c - 1, c_lo, wr, wc, lane);
                if (c < 7) cp_wait0();
                __syncthreads();
            }
            epi_only(acc[1], cn16, s_s, 7, c_lo, wr, wc, lane);
        } else {
            int cls16[16];
#pragma unroll
            for (int nt = 0; nt < 8; nt++) {
                int m0 = mbase + wc * 64 + nt * 8 + (lane & 3) * 2;
                cls16[nt * 2]     = g_cls[m0];
                cls16[nt * 2 + 1] = g_cls[m0 + 1];
            }
#pragma unroll 1
            for (int chunk = 0; chunk < 8; chunk++) {
                if (chunk) {
                    __syncthreads();
                    cp_a_chunk(AB[0], chunk, tid);
                    cp_wait0();
                    __syncthreads();
                }
                mma_chunk_h(acc[0], AB[0], BB, wr, wc, lane);
                int r0 = chunk * 128 + wr * 16 + (lane >> 2);
                float hn0 = g_hn2[r0], hn1 = g_hn2[r0 + 8];
                float ev[8][4];
#pragma unroll
                for (int nt = 0; nt < 8; nt++) {
                    float2 f01 = __half22float2(*(const __half2*)&acc[0][nt][0]);
                    float2 f23 = __half22float2(*(const __half2*)&acc[0][nt][1]);
                    float sq0 = fmaxf(fmaf(-2.f, f01.x, hn0 + cn16[nt*2]),   1e-30f);
                    float sq1 = fmaxf(fmaf(-2.f, f01.y, hn0 + cn16[nt*2+1]), 1e-30f);
                    float sq2 = fmaxf(fmaf(-2.f, f23.x, hn1 + cn16[nt*2]),   1e-30f);
                    float sq3 = fmaxf(fmaf(-2.f, f23.y, hn1 + cn16[nt*2+1]), 1e-30f);
                    ev[nt][0] = __expf(-sqrt_approx(sq0));
                    ev[nt][1] = __expf(-sqrt_approx(sq1));
                    ev[nt][2] = __expf(-sqrt_approx(sq2));
                    ev[nt][3] = __expf(-sqrt_approx(sq3));
                }
                for (int cc = c_lo; cc <= c_hi; cc++) {
                    float rs[2] = {0.f, 0.f};
#pragma unroll
                    for (int nt = 0; nt < 8; nt++) {
                        rs[0] += (cls16[nt*2]   == cc) ? ev[nt][0] : 0.f;
                        rs[0] += (cls16[nt*2+1] == cc) ? ev[nt][1] : 0.f;
                        rs[1] += (cls16[nt*2]   == cc) ? ev[nt][2] : 0.f;
                        rs[1] += (cls16[nt*2+1] == cc) ? ev[nt][3] : 0.f;
                    }
                    epi_reduce_store(rs, s_s, chunk, cc, wr, wc, lane);
                }
            }
        }
    }
    __syncthreads();
    for (int i = tid; i < B_ROWS * D_OUT; i += 512)
        g_part[(size_t)blockIdx.x * (B_ROWS * D_OUT) + i] =
            s_s[i] + s_s[B_ROWS * D_OUT + i];
}

// ---------------------------------------------------------------- k_final
__global__ void k_final(float* __restrict__ out, int nctas) {
    __shared__ float red[320];
    int b = blockIdx.x, t = threadIdx.x;    // 320 threads
    int g = t / 10, c = t - g * 10;
    float s = 0.f;
    for (int p = g; p < nctas; p += 32)
        s += g_part[(size_t)p * (B_ROWS * D_OUT) + b * D_OUT + c];
    red[t] = s;
    __syncthreads();
    if (t < 160) red[t] += red[t + 160]; __syncthreads();
    if (t < 80)  red[t] += red[t + 80];  __syncthreads();
    if (t < 40)  red[t] += red[t + 40];  __syncthreads();
    if (t < 20)  red[t] += red[t + 20];  __syncthreads();
    if (t < 10)  red[t] += red[t + 10];
    __syncthreads();
    if (t < 10) {
        float tot = 0.f;
#pragma unroll
        for (int cc = 0; cc < 10; cc++) tot += red[cc];
        out[b * D_OUT + t] = logf(red[t] / tot + 1e-7f);
    }
}

// ---------------------------------------------------------------- launch
extern "C" void kernel_launch(void* const* d_in, const int* in_sizes, int n_in,
                              void* d_out, int out_size) {
    const float* x  = (const float*)d_in[0];
    const float* cx = (const float*)d_in[2];
    const int*   cy = (const int*)d_in[3];
    const float* W  = (const float*)d_in[4];
    const float* be = (const float*)d_in[5];
    float* out = (float*)d_out;

    int dev = 0;
    cudaGetDevice(&dev);
    int nsm = 148;
    cudaDeviceGetAttribute(&nsm, cudaDevAttrMultiProcessorCount, dev);
    if (nsm < 1 || nsm > MAX_CTAS) nsm = 148;

    cudaFuncSetAttribute(k_hq,   cudaFuncAttributeMaxDynamicSharedMemorySize, SMEM_HC_BYTES);
    cudaFuncSetAttribute(k_hc,   cudaFuncAttributeMaxDynamicSharedMemorySize, SMEM_HC_BYTES);
    cudaFuncSetAttribute(k_main, cudaFuncAttributeMaxDynamicSharedMemorySize, SMEM_MAIN_BYTES);

    k_hist<<<NBLK, 256>>>(cy);
    k_scan<<<1, 32>>>();
    k_rank<<<NBLK, 256>>>(cy);
    k_hq<<<8, 512, SMEM_HC_BYTES>>>(x, W, be);
    k_hc<<<N_MT, 512, SMEM_HC_BYTES>>>(cx, W, be);
    k_main<<<nsm, 512, SMEM_MAIN_BYTES>>>();
    k_final<<<B_ROWS, 320>>>(out, nsm);
}

// round 8
// speedup vs baseline: 1.0838x; 1.0838x over previous
#include <cuda_runtime.h>
#include <cuda_fp16.h>
#include <math.h>
#include <stdint.h>

#define B_ROWS 1024
#define M_TOT  200000
#define D_INP  256
#define DIM    128
#define D_OUT  10
#define M_PAD  200192            /* 782*256 = 1564*128 */
#define N_HCT  1564              /* projection tiles of 128 */
#define N_MT2  782               /* k_main m-tiles of 256 */
#define NBLK   782               /* histogram blocks of 256 */
#define MAX_CTAS 512

// ---------------------------------------------------------------- helpers
__device__ __forceinline__ uint32_t smem_to_u32(const void* p) {
    uint32_t a;
    asm("{ .reg .u64 t; cvta.to.shared.u64 t, %1; cvt.u32.u64 %0, t; }"
        : "=r"(a) : "l"(p));
    return a;
}
__device__ __forceinline__ void ldsm4(uint32_t r[4], uint32_t addr) {
    asm volatile("ldmatrix.sync.aligned.m8n8.x4.shared.b16 {%0,%1,%2,%3}, [%4];"
                 : "=r"(r[0]), "=r"(r[1]), "=r"(r[2]), "=r"(r[3]) : "r"(addr));
}
__device__ __forceinline__ void mma16816(float c[4], const uint32_t a[4],
                                         const uint32_t b0, const uint32_t b1) {
    asm volatile("mma.sync.aligned.m16n8k16.row.col.f32.f16.f16.f32 "
                 "{%0,%1,%2,%3}, {%4,%5,%6,%7}, {%8,%9}, {%0,%1,%2,%3};"
                 : "+f"(c[0]), "+f"(c[1]), "+f"(c[2]), "+f"(c[3])
                 : "r"(a[0]), "r"(a[1]), "r"(a[2]), "r"(a[3]), "r"(b0), "r"(b1));
}
__device__ __forceinline__ float sqrt_approx(float x) {
    float r; asm("sqrt.approx.f32 %0, %1;" : "=f"(r) : "f"(x)); return r;
}
// A-fragment ldmatrix (16 rows x 16 k)
__device__ __forceinline__ void lda_frag(uint32_t a[4], uint32_t base, int R0,
                                         int ks, int lane, int rstride) {
    int row = R0 + (lane & 15);
    int kb  = ks * 32 + ((lane >> 4) << 4);
    ldsm4(a, base + row * rstride + (kb ^ ((row & 7) << 4)));
}
// B-fragment ldmatrix: two n-tiles of 8
__device__ __forceinline__ void ldb_frag(uint32_t b[4], uint32_t base, int N0,
                                         int ks, int lane, int rstride) {
    int row = N0 + (lane & 7) + ((lane >> 4) << 3);
    int kb  = ks * 32 + ((lane >> 3) & 1) * 16;
    ldsm4(b, base + row * rstride + (kb ^ ((row & 7) << 4)));
}

// ---------------------------------------------------------------- scratch
__device__ __half g_h   [B_ROWS * DIM];
__device__ float  g_hn2 [B_ROWS];
__device__ __half g_hc  [(size_t)M_PAD * DIM];
__device__ float  g_hcn2[M_PAD];
__device__ int    g_src [M_PAD];
__device__ int    g_cls [M_PAD];
__device__ int    g_bh  [NBLK * D_OUT];
__device__ int    g_boff[NBLK * D_OUT];
__device__ int    g_coff[D_OUT];
__device__ float  g_part[(size_t)MAX_CTAS * B_ROWS * D_OUT];

// ---------------------------------------------------------------- sort
__global__ void k_hist(const int* __restrict__ cy) {
    __shared__ int cnt[D_OUT];
    int t = threadIdx.x, b = blockIdx.x;
    if (t < D_OUT) cnt[t] = 0;
    __syncthreads();
    int m = b * 256 + t;
    if (m < M_TOT) atomicAdd(&cnt[cy[m]], 1);
    __syncthreads();
    if (t < D_OUT) g_bh[b * D_OUT + t] = cnt[t];
}
__global__ void k_scan() {
    __shared__ int tot[D_OUT];
    int t = threadIdx.x;
    if (t < D_OUT) {
        int run = 0;
        for (int b = 0; b < NBLK; b++) {
            int v = g_bh[b * D_OUT + t];
            g_boff[b * D_OUT + t] = run;
            run += v;
        }
        tot[t] = run;
    }
    __syncthreads();
    if (t == 0) {
        int off = 0;
        for (int c = 0; c < D_OUT; c++) { g_coff[c] = off; off += tot[c]; }
        for (int p = M_TOT; p < M_PAD; p++) g_cls[p] = D_OUT - 1;
    }
}
__global__ void k_rank(const int* __restrict__ cy) {
    __shared__ int cls[256];
    int t = threadIdx.x, b = blockIdx.x;
    int m = b * 256 + t;
    int c = (m < M_TOT) ? cy[m] : -1;
    cls[t] = c;
    __syncthreads();
    if (m < M_TOT) {
        int r = 0;
        for (int j = 0; j < t; j++) r += (cls[j] == c);
        int pos = g_coff[c] + g_boff[b * D_OUT + c] + r;
        g_src[pos] = m;
        g_cls[pos] = c;
    }
}

// ---------------------------------------------------------------- projection
#define HC_A 0
#define HC_B 65536
#define HC_BIAS 131072
#define HC_SRC  131584
#define HC_PART 132096
#define SMEM_HC_BYTES (HC_PART + 1024)

template <bool GATHER>
__device__ __forceinline__ void proj_body(const float* __restrict__ src_mat,
                                          const float* __restrict__ W,
                                          __half* __restrict__ out_h,
                                          float* __restrict__ out_n2,
                                          int tile, bool pad_check) {
    extern __shared__ char smem[];
    uint32_t sb = smem_to_u32(smem);
    float* bias_s = (float*)(smem + HC_BIAS);
    int*   srcs   = (int*)(smem + HC_SRC);
    float* part   = (float*)(smem + HC_PART);
    int tid = threadIdx.x, lane = tid & 31, wid = tid >> 5;
    int wr = wid & 7, wc = wid >> 3;

    __syncthreads();   // srcs/bias ready (caller filled)

#pragma unroll
    for (int i = 0; i < 8; i++) {
        int idx = tid + i * 512;
        int r = idx >> 5, kb = (idx & 31) * 16;
        size_t srow = GATHER ? (size_t)srcs[r] : ((size_t)tile * 128 + r);
        const float4* s4 = (const float4*)(src_mat + srow * D_INP + kb / 2);
        float4 v0 = s4[0], v1 = s4[1];
        __half2 h0 = __floats2half2_rn(v0.x, v0.y), h1 = __floats2half2_rn(v0.z, v0.w);
        __half2 h2 = __floats2half2_rn(v1.x, v1.y), h3 = __floats2half2_rn(v1.z, v1.w);
        *(uint4*)(smem + HC_A + r * 512 + (kb ^ ((r & 7) << 4))) =
            make_uint4(*(uint32_t*)&h0, *(uint32_t*)&h1, *(uint32_t*)&h2, *(uint32_t*)&h3);
    }
#pragma unroll
    for (int i = 0; i < 8; i++) {
        int idx = tid + i * 512;
        int r = idx >> 5, kb = (idx & 31) * 16;
        const float4* s4 = (const float4*)(W + (size_t)r * D_INP + kb / 2);
        float4 v0 = s4[0], v1 = s4[1];
        __half2 h0 = __floats2half2_rn(v0.x, v0.y), h1 = __floats2half2_rn(v0.z, v0.w);
        __half2 h2 = __floats2half2_rn(v1.x, v1.y), h3 = __floats2half2_rn(v1.z, v1.w);
        *(uint4*)(smem + HC_B + r * 512 + (kb ^ ((r & 7) << 4))) =
            make_uint4(*(uint32_t*)&h0, *(uint32_t*)&h1, *(uint32_t*)&h2, *(uint32_t*)&h3);
    }
    __syncthreads();

    float acc[8][4];
#pragma unroll
    for (int n = 0; n < 8; n++)
#pragma unroll
        for (int j = 0; j < 4; j++) acc[n][j] = 0.f;
#pragma unroll
    for (int ks = 0; ks < 16; ks++) {
        uint32_t a[4], bf[4][4];
        lda_frag(a, sb + HC_A, wr * 16, ks, lane, 512);
#pragma unroll
        for (int p = 0; p < 4; p++)
            ldb_frag(bf[p], sb + HC_B, wc * 64 + p * 16, ks, lane, 512);
#pragma unroll
        for (int nt = 0; nt < 8; nt++)
            mma16816(acc[nt], a, bf[nt >> 1][(nt & 1) * 2], bf[nt >> 1][(nt & 1) * 2 + 1]);
    }

    float sumsq[2] = {0.f, 0.f};
#pragma unroll
    for (int hr = 0; hr < 2; hr++) {
        int row = wr * 16 + (lane >> 2) + hr * 8;
        size_t gm = (size_t)tile * 128 + row;
#pragma unroll
        for (int nt = 0; nt < 8; nt++) {
            int d0 = wc * 64 + nt * 8 + (lane & 3) * 2;
            float v0 = acc[nt][hr * 2 + 0] + bias_s[d0];
            float v1 = acc[nt][hr * 2 + 1] + bias_s[d0 + 1];
            __half2 hp = __floats2half2_rn(v0, v1);
            float2 vr = __half22float2(hp);
            sumsq[hr] = fmaf(vr.x, vr.x, sumsq[hr]);
            sumsq[hr] = fmaf(vr.y, vr.y, sumsq[hr]);
            *(__half2*)(out_h + gm * DIM + d0) = hp;
        }
    }
#pragma unroll
    for (int hr = 0; hr < 2; hr++) {
        float v = sumsq[hr];
        v += __shfl_xor_sync(0xFFFFFFFF, v, 1);
        v += __shfl_xor_sync(0xFFFFFFFF, v, 2);
        if ((lane & 3) == 0) {
            int row = wr * 16 + (lane >> 2) + hr * 8;
            part[row * 2 + wc] = v;
        }
    }
    __syncthreads();
    if (tid < 128) {
        size_t gm = (size_t)tile * 128 + tid;
        float v = part[tid * 2] + part[tid * 2 + 1];
        out_n2[gm] = (!pad_check || gm < M_TOT) ? v : 3e38f;
    }
}

// merged projection: blocks [0,8) do queries, [8, 8+N_HCT) do candidates
__global__ __launch_bounds__(512, 1) void k_proj(const float* __restrict__ x,
                                                 const float* __restrict__ cx,
                                                 const float* __restrict__ W,
                                                 const float* __restrict__ be) {
    extern __shared__ char smem[];
    float* bias_s = (float*)(smem + HC_BIAS);
    int*   srcs   = (int*)(smem + HC_SRC);
    int tid = threadIdx.x;
    if ((int)blockIdx.x < 8) {
        int tile = blockIdx.x;
        if (tid < 128) bias_s[tid] = be[tid];
        proj_body<false>(x, W, g_h, g_hn2, tile, false);
    } else {
        int tile = blockIdx.x - 8;
        if (tid < 128) {
            int p = tile * 128 + tid;
            srcs[tid]   = (p < M_TOT) ? g_src[p] : 0;
            bias_s[tid] = be[tid];
        }
        proj_body<true>(cx, W, g_hc, g_hcn2, tile, true);
    }
}

// ---------------------------------------------------------------- k_main
// 512 threads / 16 warps: wr=wid&7 (16-row strip of 128 A-rows), wc=wid>>3
// m-tile = 256 candidates (two 128-col halves sharing each A chunk)
#define KM_A0  0
#define KM_A1  32768
#define KM_B   65536       /* 256 rows x 256B = 64KB */
#define KM_CN  131072      /* 256 f32 */
#define KM_CLS 132096      /* 256 i32 */
#define KM_SS  133120      /* 2 x 1024 x 10 f32 = 80KB */
#define SMEM_MAIN_BYTES (KM_SS + 2 * B_ROWS * D_OUT * 4)

__device__ __forceinline__ void load_a_chunk(char* smem, int off, int chunk, int tid) {
#pragma unroll
    for (int i = 0; i < 4; i++) {
        int idx = tid + i * 512;
        int r = idx >> 4, kb = (idx & 15) * 16;
        *(uint4*)(smem + off + r * 256 + (kb ^ ((r & 7) << 4))) =
            *(const uint4*)((const char*)g_h + ((size_t)chunk * 128 + r) * 256 + kb);
    }
}

__device__ __forceinline__ void epi_reduce_store(float (&rs)[2], float* s_s,
                                                 int cprev, int cls,
                                                 int wr, int wc, int lane) {
#pragma unroll
    for (int hr = 0; hr < 2; hr++) {
        float v = rs[hr];
        v += __shfl_xor_sync(0xFFFFFFFF, v, 1);
        v += __shfl_xor_sync(0xFFFFFFFF, v, 2);
        if ((lane & 3) == 0) {
            int brow = cprev * 128 + wr * 16 + (lane >> 2) + hr * 8;
            s_s[wc * (B_ROWS * D_OUT) + brow * D_OUT + cls] += v;
        }
    }
}

// one 4-element slice: rows r,r+8 x cols c,c+1 of the previous step
__device__ __forceinline__ void epi_slice(const float accP[4], float hn0, float hn1,
                                          const float* cnp, float (&rs)[2]) {
    float c0 = cnp[0], c1 = cnp[1];
    float sq0 = fmaxf(fmaf(-2.f, accP[0], hn0 + c0), 1e-30f);
    float sq1 = fmaxf(fmaf(-2.f, accP[1], hn0 + c1), 1e-30f);
    float sq2 = fmaxf(fmaf(-2.f, accP[2], hn1 + c0), 1e-30f);
    float sq3 = fmaxf(fmaf(-2.f, accP[3], hn1 + c1), 1e-30f);
    rs[0] += __expf(-sqrt_approx(sq0)) + __expf(-sqrt_approx(sq1));
    rs[1] += __expf(-sqrt_approx(sq2)) + __expf(-sqrt_approx(sq3));
}

// plain MMA of one (chunk, half): 128x64x128 per warp-pair
__device__ __forceinline__ void mma_step(float (&acc)[8][4], uint32_t abase,
                                         uint32_t bbase, int hb,
                                         int wr, int wc, int lane) {
#pragma unroll
    for (int n = 0; n < 8; n++)
#pragma unroll
        for (int j = 0; j < 4; j++) acc[n][j] = 0.f;
#pragma unroll
    for (int ks = 0; ks < 8; ks++) {
        uint32_t a[4], bf[4][4];
        lda_frag(a, abase, wr * 16, ks, lane, 256);
#pragma unroll
        for (int p = 0; p < 4; p++)
            ldb_frag(bf[p], bbase, hb * 128 + wc * 64 + p * 16, ks, lane, 256);
#pragma unroll
        for (int nt = 0; nt < 8; nt++)
            mma16816(acc[nt], a, bf[nt >> 1][(nt & 1) * 2], bf[nt >> 1][(nt & 1) * 2 + 1]);
    }
}

// MMA of step (chunk cN, half hbN) interleaved with epilogue of (cP, hbP)
__device__ __forceinline__ void mma_step_epi(float (&accN)[8][4],
                                             const float (&accP)[8][4],
                                             uint32_t abase, uint32_t bbase, int hbN,
                                             const float* cn_s, int cP, int hbP,
                                             float* s_s, int cls,
                                             int wr, int wc, int lane) {
    int r0 = cP * 128 + wr * 16 + (lane >> 2);
    float hn0 = g_hn2[r0], hn1 = g_hn2[r0 + 8];
    const float* cnp = cn_s + hbP * 128 + wc * 64 + (lane & 3) * 2;
    float rs[2] = {0.f, 0.f};
#pragma unroll
    for (int n = 0; n < 8; n++)
#pragma unroll
        for (int j = 0; j < 4; j++) accN[n][j] = 0.f;
#pragma unroll
    for (int ks = 0; ks < 8; ks++) {
        uint32_t a[4], bf[4][4];
        lda_frag(a, abase, wr * 16, ks, lane, 256);
#pragma unroll
        for (int p = 0; p < 4; p++)
            ldb_frag(bf[p], bbase, hbN * 128 + wc * 64 + p * 16, ks, lane, 256);
#pragma unroll
        for (int nt = 0; nt < 8; nt++)
            mma16816(accN[nt], a, bf[nt >> 1][(nt & 1) * 2], bf[nt >> 1][(nt & 1) * 2 + 1]);
        epi_slice(accP[ks], hn0, hn1, cnp + ks * 8, rs);
    }
    epi_reduce_store(rs, s_s, cP, cls, wr, wc, lane);
}

__device__ __forceinline__ void epi_only(const float (&accP)[8][4],
                                         const float* cn_s, int cP, int hbP,
                                         float* s_s, int cls,
                                         int wr, int wc, int lane) {
    int r0 = cP * 128 + wr * 16 + (lane >> 2);
    float hn0 = g_hn2[r0], hn1 = g_hn2[r0 + 8];
    const float* cnp = cn_s + hbP * 128 + wc * 64 + (lane & 3) * 2;
    float rs[2] = {0.f, 0.f};
#pragma unroll
    for (int nt = 0; nt < 8; nt++)
        epi_slice(accP[nt], hn0, hn1, cnp + nt * 8, rs);
    epi_reduce_store(rs, s_s, cP, cls, wr, wc, lane);
}

__global__ __launch_bounds__(512, 1) void k_main() {
    extern __shared__ char smem[];
    uint32_t sb = smem_to_u32(smem);
    float* s_s  = (float*)(smem + KM_SS);
    float* cn_s = (float*)(smem + KM_CN);
    int*   cls_s = (int*)(smem + KM_CLS);
    int tid = threadIdx.x, lane = tid & 31, wid = tid >> 5;
    int wr = wid & 7, wc = wid >> 3;
    uint32_t AB[2] = {sb + KM_A0, sb + KM_A1};
    uint32_t BB = sb + KM_B;

    for (int i = tid; i < 2 * B_ROWS * D_OUT; i += 512) s_s[i] = 0.f;

    float acc0[8][4], acc1[8][4];

    for (int mt = blockIdx.x; mt < N_MT2; mt += gridDim.x) {
        __syncthreads();   // prior mt fully done before smem overwrite
        int mbase = mt * 256;
        // B tile: 256 hc rows (4096 x 16B over 512 threads)
#pragma unroll
        for (int i = 0; i < 8; i++) {
            int idx = tid + i * 512;
            int r = idx >> 4, kb = (idx & 15) * 16;
            *(uint4*)(smem + KM_B + r * 256 + (kb ^ ((r & 7) << 4))) =
                *(const uint4*)((const char*)g_hc + ((size_t)mbase + r) * 256 + kb);
        }
        load_a_chunk(smem, KM_A0, 0, tid);
        if (tid < 256) {
            cn_s[tid]  = g_hcn2[mbase + tid];
            cls_s[tid] = g_cls[mbase + tid];
        }
        int c_lo = g_cls[mbase], c_hi = g_cls[mbase + 255];
        __syncthreads();

        if (c_lo == c_hi) {
            // s=0: chunk0/half0 -> acc0 ; prefetch chunk1 -> A1
            load_a_chunk(smem, KM_A1, 1, tid);
            mma_step(acc0, AB[0], BB, 0, wr, wc, lane);
            // s=1: chunk0/half1 -> acc1, epi(chunk0, half0)
            mma_step_epi(acc1, acc0, AB[0], BB, 1, cn_s, 0, 0, s_s, c_lo, wr, wc, lane);
            __syncthreads();
#pragma unroll 1
            for (int c = 1; c < 8; c++) {
                if (c < 7) load_a_chunk(smem, (int)(((c + 1) & 1) ? KM_A1 : KM_A0), c + 1, tid);
                // s=2c: chunk c half0 -> acc0, epi(chunk c-1, half1)=acc1
                mma_step_epi(acc0, acc1, AB[c & 1], BB, 0, cn_s, c - 1, 1,
                             s_s, c_lo, wr, wc, lane);
                // s=2c+1: chunk c half1 -> acc1, epi(chunk c, half0)=acc0
                mma_step_epi(acc1, acc0, AB[c & 1], BB, 1, cn_s, c, 0,
                             s_s, c_lo, wr, wc, lane);
                __syncthreads();
            }
            epi_only(acc1, cn_s, 7, 1, s_s, c_lo, wr, wc, lane);
        } else {
            // mixed-class tile (rare: <=9 of 782)
#pragma unroll 1
            for (int chunk = 0; chunk < 8; chunk++) {
                if (chunk) {
                    __syncthreads();
                    load_a_chunk(smem, KM_A0, chunk, tid);
                    __syncthreads();
                }
                int r0 = chunk * 128 + wr * 16 + (lane >> 2);
                float hn0 = g_hn2[r0], hn1 = g_hn2[r0 + 8];
#pragma unroll 1
                for (int hb = 0; hb < 2; hb++) {
                    mma_step(acc0, AB[0], BB, hb, wr, wc, lane);
                    float ev[8][4];
                    int cb = hb * 128 + wc * 64 + (lane & 3) * 2;
#pragma unroll
                    for (int nt = 0; nt < 8; nt++) {
                        float c0 = cn_s[cb + nt * 8], c1 = cn_s[cb + nt * 8 + 1];
                        float sq0 = fmaxf(fmaf(-2.f, acc0[nt][0], hn0 + c0), 1e-30f);
                        float sq1 = fmaxf(fmaf(-2.f, acc0[nt][1], hn0 + c1), 1e-30f);
                        float sq2 = fmaxf(fmaf(-2.f, acc0[nt][2], hn1 + c0), 1e-30f);
                        float sq3 = fmaxf(fmaf(-2.f, acc0[nt][3], hn1 + c1), 1e-30f);
                        ev[nt][0] = __expf(-sqrt_approx(sq0));
                        ev[nt][1] = __expf(-sqrt_approx(sq1));
                        ev[nt][2] = __expf(-sqrt_approx(sq2));
                        ev[nt][3] = __expf(-sqrt_approx(sq3));
                    }
                    for (int cc = c_lo; cc <= c_hi; cc++) {
                        float rs[2] = {0.f, 0.f};
#pragma unroll
                        for (int nt = 0; nt < 8; nt++) {
                            int cl0 = cls_s[cb + nt * 8], cl1 = cls_s[cb + nt * 8 + 1];
                            rs[0] += (cl0 == cc) ? ev[nt][0] : 0.f;
                            rs[0] += (cl1 == cc) ? ev[nt][1] : 0.f;
                            rs[1] += (cl0 == cc) ? ev[nt][2] : 0.f;
                            rs[1] += (cl1 == cc) ? ev[nt][3] : 0.f;
                        }
                        epi_reduce_store(rs, s_s, chunk, cc, wr, wc, lane);
                    }
                }
            }
        }
    }
    __syncthreads();
    for (int i = tid; i < B_ROWS * D_OUT; i += 512)
        g_part[(size_t)blockIdx.x * (B_ROWS * D_OUT) + i] =
            s_s[i] + s_s[B_ROWS * D_OUT + i];
}

// ---------------------------------------------------------------- k_final
__global__ void k_final(float* __restrict__ out, int nctas) {
    __shared__ float red[320];
    int b = blockIdx.x, t = threadIdx.x;    // 320 threads
    int g = t / 10, c = t - g * 10;
    float s = 0.f;
    for (int p = g; p < nctas; p += 32)
        s += g_part[(size_t)p * (B_ROWS * D_OUT) + b * D_OUT + c];
    red[t] = s;
    __syncthreads();
    if (t < 160) red[t] += red[t + 160]; __syncthreads();
    if (t < 80)  red[t] += red[t + 80];  __syncthreads();
    if (t < 40)  red[t] += red[t + 40];  __syncthreads();
    if (t < 20)  red[t] += red[t + 20];  __syncthreads();
    if (t < 10)  red[t] += red[t + 10];
    __syncthreads();
    if (t < 10) {
        float tot = 0.f;
#pragma unroll
        for (int cc = 0; cc < 10; cc++) tot += red[cc];
        out[b * D_OUT + t] = logf(red[t] / tot + 1e-7f);
    }
}

// ---------------------------------------------------------------- launch
extern "C" void kernel_launch(void* const* d_in, const int* in_sizes, int n_in,
                              void* d_out, int out_size) {
    const float* x  = (const float*)d_in[0];
    const float* cx = (const float*)d_in[2];
    const int*   cy = (const int*)d_in[3];
    const float* W  = (const float*)d_in[4];
    const float* be = (const float*)d_in[5];
    float* out = (float*)d_out;

    int dev = 0;
    cudaGetDevice(&dev);
    int nsm = 148;
    cudaDeviceGetAttribute(&nsm, cudaDevAttrMultiProcessorCount, dev);
    if (nsm < 1 || nsm > MAX_CTAS) nsm = 148;

    cudaFuncSetAttribute(k_proj, cudaFuncAttributeMaxDynamicSharedMemorySize, SMEM_HC_BYTES);
    cudaFuncSetAttribute(k_main, cudaFuncAttributeMaxDynamicSharedMemorySize, SMEM_MAIN_BYTES);

    k_hist<<<NBLK, 256>>>(cy);
    k_scan<<<1, 32>>>();
    k_rank<<<NBLK, 256>>>(cy);
    k_proj<<<N_HCT + 8, 512, SMEM_HC_BYTES>>>(x, cx, W, be);
    k_main<<<nsm, 512, SMEM_MAIN_BYTES>>>();
    k_final<<<B_ROWS, 320>>>(out, nsm);
}

// round 9
// speedup vs baseline: 1.2922x; 1.1923x over previous
#include <cuda_runtime.h>
#include <cuda_fp16.h>
#include <math.h>
#include <stdint.h>

#define B_ROWS 1024
#define M_TOT  200000
#define D_INP  256
#define DIM    128
#define D_OUT  10
#define M_PAD  200192            /* 1564*128 = 3128*64 */
#define N_MT   1564              /* k_main m-tiles of 128 */
#define N_PCT  3128              /* projection candidate tiles of 64 */
#define NBLK   782               /* histogram blocks of 256 */
#define MAX_CTAS 512

// ---------------------------------------------------------------- helpers
__device__ __forceinline__ uint32_t smem_to_u32(const void* p) {
    uint32_t a;
    asm("{ .reg .u64 t; cvta.to.shared.u64 t, %1; cvt.u32.u64 %0, t; }"
        : "=r"(a) : "l"(p));
    return a;
}
__device__ __forceinline__ void ldsm4(uint32_t r[4], uint32_t addr) {
    asm volatile("ldmatrix.sync.aligned.m8n8.x4.shared.b16 {%0,%1,%2,%3}, [%4];"
                 : "=r"(r[0]), "=r"(r[1]), "=r"(r[2]), "=r"(r[3]) : "r"(addr));
}
__device__ __forceinline__ void mma16816(float c[4], const uint32_t a[4],
                                         const uint32_t b0, const uint32_t b1) {
    asm volatile("mma.sync.aligned.m16n8k16.row.col.f32.f16.f16.f32 "
                 "{%0,%1,%2,%3}, {%4,%5,%6,%7}, {%8,%9}, {%0,%1,%2,%3};"
                 : "+f"(c[0]), "+f"(c[1]), "+f"(c[2]), "+f"(c[3])
                 : "r"(a[0]), "r"(a[1]), "r"(a[2]), "r"(a[3]), "r"(b0), "r"(b1));
}
__device__ __forceinline__ float sqrt_approx(float x) {
    float r; asm("sqrt.approx.f32 %0, %1;" : "=f"(r) : "f"(x)); return r;
}
// A-fragment ldmatrix (16 rows x 16 k)
__device__ __forceinline__ void lda_frag(uint32_t a[4], uint32_t base, int R0,
                                         int ks, int lane, int rstride) {
    int row = R0 + (lane & 15);
    int kb  = ks * 32 + ((lane >> 4) << 4);
    ldsm4(a, base + row * rstride + (kb ^ ((row & 7) << 4)));
}
// B-fragment ldmatrix: two n-tiles of 8
__device__ __forceinline__ void ldb_frag(uint32_t b[4], uint32_t base, int N0,
                                         int ks, int lane, int rstride) {
    int row = N0 + (lane & 7) + ((lane >> 4) << 3);
    int kb  = ks * 32 + ((lane >> 3) & 1) * 16;
    ldsm4(b, base + row * rstride + (kb ^ ((row & 7) << 4)));
}

// ---------------------------------------------------------------- scratch
__device__ __half g_h   [B_ROWS * DIM];
__device__ float  g_hn2 [B_ROWS];
__device__ __half g_hc  [(size_t)M_PAD * DIM];
__device__ float  g_hcn2[M_PAD];
__device__ int    g_src [M_PAD];
__device__ int    g_cls [M_PAD];
__device__ int    g_bh  [NBLK * D_OUT];
__device__ int    g_boff[NBLK * D_OUT];
__device__ int    g_coff[D_OUT];
__device__ float  g_part[(size_t)MAX_CTAS * B_ROWS * D_OUT];

// ---------------------------------------------------------------- sort
__global__ void k_hist(const int* __restrict__ cy) {
    __shared__ int cnt[D_OUT];
    int t = threadIdx.x, b = blockIdx.x;
    if (t < D_OUT) cnt[t] = 0;
    __syncthreads();
    int m = b * 256 + t;
    if (m < M_TOT) atomicAdd(&cnt[cy[m]], 1);
    __syncthreads();
    if (t < D_OUT) g_bh[b * D_OUT + t] = cnt[t];
}
// 320 threads: warp w scans class w across 782 blocks (25 shuffle-scan rounds)
__global__ void k_scan() {
    __shared__ int tot[D_OUT];
    int w = threadIdx.x >> 5, lane = threadIdx.x & 31;
    if (w < D_OUT) {
        int run = 0;
        for (int base = 0; base < NBLK; base += 32) {
            int b = base + lane;
            int v = (b < NBLK) ? g_bh[b * D_OUT + w] : 0;
            int s = v;
#pragma unroll
            for (int o = 1; o < 32; o <<= 1) {
                int t = __shfl_up_sync(0xFFFFFFFF, s, o);
                if (lane >= o) s += t;
            }
            if (b < NBLK) g_boff[b * D_OUT + w] = run + s - v;
            run += __shfl_sync(0xFFFFFFFF, s, 31);
        }
        if (lane == 0) tot[w] = run;
    }
    __syncthreads();
    if (threadIdx.x == 0) {
        int off = 0;
        for (int c = 0; c < D_OUT; c++) { g_coff[c] = off; off += tot[c]; }
    }
    for (int p = M_TOT + threadIdx.x; p < M_PAD; p += 320) g_cls[p] = D_OUT - 1;
}
__global__ void k_rank(const int* __restrict__ cy) {
    __shared__ int cls[256];
    int t = threadIdx.x, b = blockIdx.x;
    int m = b * 256 + t;
    int c = (m < M_TOT) ? cy[m] : -1;
    cls[t] = c;
    __syncthreads();
    if (m < M_TOT) {
        int r = 0;
        for (int j = 0; j < t; j++) r += (cls[j] == c);
        int pos = g_coff[c] + g_boff[b * D_OUT + c] + r;
        g_src[pos] = m;
        g_cls[pos] = c;
    }
}

// ---------------------------------------------------------------- k_proj
// 64-row tiles, 256 threads, ~99KB smem -> 2 CTAs/SM.
// warps: wr=wid&3 (16-row strip), wc=wid>>2 (64-col half)
#define P_A    0        /* 64 x 512B  = 32KB  */
#define P_B    32768    /* 128 x 512B = 64KB  */
#define P_BIAS 98304    /* 512B */
#define P_SRC  98816    /* 256B */
#define P_PART 99072    /* 512B */
#define SMEM_P_BYTES 99584

__global__ __launch_bounds__(256, 2) void k_proj(const float* __restrict__ x,
                                                 const float* __restrict__ cx,
                                                 const float* __restrict__ W,
                                                 const float* __restrict__ be) {
    extern __shared__ char smem[];
    uint32_t sb = smem_to_u32(smem);
    float* bias_s = (float*)(smem + P_BIAS);
    int*   srcs   = (int*)(smem + P_SRC);
    float* part   = (float*)(smem + P_PART);
    int tid = threadIdx.x, lane = tid & 31, wid = tid >> 5;
    int wr = wid & 3, wc = wid >> 2;
    bool isq = (int)blockIdx.x < 16;
    int tile = isq ? (int)blockIdx.x : (int)blockIdx.x - 16;

    if (tid < 128) bias_s[tid] = be[tid];
    if (!isq && tid < 64) {
        int p = tile * 64 + tid;
        srcs[tid] = (p < M_TOT) ? g_src[p] : 0;
    }
    __syncthreads();

    const float* src_mat = isq ? x : cx;
    // A: 64 rows x 256 k fp32->fp16 (2048 x 16B over 256 thr)
#pragma unroll
    for (int i = 0; i < 8; i++) {
        int idx = tid + i * 256;
        int r = idx >> 5, kb = (idx & 31) * 16;
        size_t srow = isq ? (size_t)(tile * 64 + r) : (size_t)srcs[r];
        const float4* s4 = (const float4*)(src_mat + srow * D_INP + kb / 2);
        float4 v0 = s4[0], v1 = s4[1];
        __half2 h0 = __floats2half2_rn(v0.x, v0.y), h1 = __floats2half2_rn(v0.z, v0.w);
        __half2 h2 = __floats2half2_rn(v1.x, v1.y), h3 = __floats2half2_rn(v1.z, v1.w);
        *(uint4*)(smem + P_A + r * 512 + (kb ^ ((r & 7) << 4))) =
            make_uint4(*(uint32_t*)&h0, *(uint32_t*)&h1, *(uint32_t*)&h2, *(uint32_t*)&h3);
    }
    // B: W (128 d x 256 k) (4096 x 16B over 256 thr)
#pragma unroll
    for (int i = 0; i < 16; i++) {
        int idx = tid + i * 256;
        int r = idx >> 5, kb = (idx & 31) * 16;
        const float4* s4 = (const float4*)(W + (size_t)r * D_INP + kb / 2);
        float4 v0 = s4[0], v1 = s4[1];
        __half2 h0 = __floats2half2_rn(v0.x, v0.y), h1 = __floats2half2_rn(v0.z, v0.w);
        __half2 h2 = __floats2half2_rn(v1.x, v1.y), h3 = __floats2half2_rn(v1.z, v1.w);
        *(uint4*)(smem + P_B + r * 512 + (kb ^ ((r & 7) << 4))) =
            make_uint4(*(uint32_t*)&h0, *(uint32_t*)&h1, *(uint32_t*)&h2, *(uint32_t*)&h3);
    }
    __syncthreads();

    float acc[8][4];
#pragma unroll
    for (int n = 0; n < 8; n++)
#pragma unroll
        for (int j = 0; j < 4; j++) acc[n][j] = 0.f;
#pragma unroll
    for (int ks = 0; ks < 16; ks++) {
        uint32_t a[4], bf[4][4];
        lda_frag(a, sb + P_A, wr * 16, ks, lane, 512);
#pragma unroll
        for (int p = 0; p < 4; p++)
            ldb_frag(bf[p], sb + P_B, wc * 64 + p * 16, ks, lane, 512);
#pragma unroll
        for (int nt = 0; nt < 8; nt++)
            mma16816(acc[nt], a, bf[nt >> 1][(nt & 1) * 2], bf[nt >> 1][(nt & 1) * 2 + 1]);
    }

    __half* out_h  = isq ? g_h   : g_hc;
    float*  out_n2 = isq ? g_hn2 : g_hcn2;
    float sumsq[2] = {0.f, 0.f};
#pragma unroll
    for (int hr = 0; hr < 2; hr++) {
        int row = wr * 16 + (lane >> 2) + hr * 8;
        size_t gm = (size_t)tile * 64 + row;
#pragma unroll
        for (int nt = 0; nt < 8; nt++) {
            int d0 = wc * 64 + nt * 8 + (lane & 3) * 2;
            float v0 = acc[nt][hr * 2 + 0] + bias_s[d0];
            float v1 = acc[nt][hr * 2 + 1] + bias_s[d0 + 1];
            __half2 hp = __floats2half2_rn(v0, v1);
            float2 vr = __half22float2(hp);
            sumsq[hr] = fmaf(vr.x, vr.x, sumsq[hr]);
            sumsq[hr] = fmaf(vr.y, vr.y, sumsq[hr]);
            *(__half2*)(out_h + gm * DIM + d0) = hp;
        }
    }
#pragma unroll
    for (int hr = 0; hr < 2; hr++) {
        float v = sumsq[hr];
        v += __shfl_xor_sync(0xFFFFFFFF, v, 1);
        v += __shfl_xor_sync(0xFFFFFFFF, v, 2);
        if ((lane & 3) == 0) {
            int row = wr * 16 + (lane >> 2) + hr * 8;
            part[row * 2 + wc] = v;
        }
    }
    __syncthreads();
    if (tid < 64) {
        size_t gm = (size_t)tile * 64 + tid;
        float v = part[tid * 2] + part[tid * 2 + 1];
        out_n2[gm] = (isq || gm < M_TOT) ? v : 3e38f;
    }
}

// ---------------------------------------------------------------- k_main
// 512 threads / 16 warps: wr=wid&7 (16-row strip), wc=wid>>3 (64-col half)
// unit = 128-candidate tile; per step 256 queries (two accumulator sets)
#define KM_A   0        /* 256 rows x 256B = 64KB */
#define KM_B   65536    /* 128 rows x 256B = 32KB */
#define KM_CN  98304    /* 128 f32 */
#define KM_CLS 98816    /* 128 i32 */
#define KM_SS  99328    /* 2 x 1024 x 10 f32 = 80KB */
#define SMEM_MAIN_BYTES (KM_SS + 2 * B_ROWS * D_OUT * 4)

__device__ __forceinline__ void epi_reduce_store(float (&rs)[2], float* s_s,
                                                 int brow_base, int cls,
                                                 int wc, int lane) {
#pragma unroll
    for (int hr = 0; hr < 2; hr++) {
        float v = rs[hr];
        v += __shfl_xor_sync(0xFFFFFFFF, v, 1);
        v += __shfl_xor_sync(0xFFFFFFFF, v, 2);
        if ((lane & 3) == 0) {
            int brow = brow_base + (lane >> 2) + hr * 8;
            s_s[wc * (B_ROWS * D_OUT) + brow * D_OUT + cls] += v;
        }
    }
}

__device__ __forceinline__ void epi_slice(const float accP[4], float hn0, float hn1,
                                          float c0, float c1, float (&rs)[2]) {
    float sq0 = fmaxf(fmaf(-2.f, accP[0], hn0 + c0), 1e-30f);
    float sq1 = fmaxf(fmaf(-2.f, accP[1], hn0 + c1), 1e-30f);
    float sq2 = fmaxf(fmaf(-2.f, accP[2], hn1 + c0), 1e-30f);
    float sq3 = fmaxf(fmaf(-2.f, accP[3], hn1 + c1), 1e-30f);
    rs[0] += __expf(-sqrt_approx(sq0)) + __expf(-sqrt_approx(sq1));
    rs[1] += __expf(-sqrt_approx(sq2)) + __expf(-sqrt_approx(sq3));
}

// dual MMA: 256 A-rows (lo strip wr*16, hi strip 128+wr*16), shared ldb
__device__ __forceinline__ void mma2(float (&aL)[8][4], float (&aH)[8][4],
                                     uint32_t A, uint32_t B,
                                     int wr, int wc, int lane) {
#pragma unroll
    for (int n = 0; n < 8; n++)
#pragma unroll
        for (int j = 0; j < 4; j++) { aL[n][j] = 0.f; aH[n][j] = 0.f; }
#pragma unroll
    for (int ks = 0; ks < 8; ks++) {
        uint32_t alo[4], ahi[4], bf[4][4];
        lda_frag(alo, A, wr * 16,       ks, lane, 256);
        lda_frag(ahi, A, 128 + wr * 16, ks, lane, 256);
#pragma unroll
        for (int p = 0; p < 4; p++)
            ldb_frag(bf[p], B, wc * 64 + p * 16, ks, lane, 256);
#pragma unroll
        for (int nt = 0; nt < 8; nt++) {
            mma16816(aL[nt], alo, bf[nt >> 1][(nt & 1) * 2], bf[nt >> 1][(nt & 1) * 2 + 1]);
            mma16816(aH[nt], ahi, bf[nt >> 1][(nt & 1) * 2], bf[nt >> 1][(nt & 1) * 2 + 1]);
        }
    }
}

// in-place exp epilogue for one acc set (mixed-class path)
__device__ __forceinline__ void exp_inplace(float (&a)[8][4], float hn0, float hn1,
                                            const float* cnp) {
#pragma unroll
    for (int nt = 0; nt < 8; nt++) {
        float c0 = cnp[nt * 8], c1 = cnp[nt * 8 + 1];
        float sq0 = fmaxf(fmaf(-2.f, a[nt][0], hn0 + c0), 1e-30f);
        float sq1 = fmaxf(fmaf(-2.f, a[nt][1], hn0 + c1), 1e-30f);
        float sq2 = fmaxf(fmaf(-2.f, a[nt][2], hn1 + c0), 1e-30f);
        float sq3 = fmaxf(fmaf(-2.f, a[nt][3], hn1 + c1), 1e-30f);
        a[nt][0] = __expf(-sqrt_approx(sq0));
        a[nt][1] = __expf(-sqrt_approx(sq1));
        a[nt][2] = __expf(-sqrt_approx(sq2));
        a[nt][3] = __expf(-sqrt_approx(sq3));
    }
}

__global__ __launch_bounds__(512, 1) void k_main() {
    extern __shared__ char smem[];
    uint32_t sb = smem_to_u32(smem);
    float* s_s   = (float*)(smem + KM_SS);
    float* cn_s  = (float*)(smem + KM_CN);
    int*   cls_s = (int*)(smem + KM_CLS);
    int tid = threadIdx.x, lane = tid & 31, wid = tid >> 5;
    int wr = wid & 7, wc = wid >> 3;
    uint32_t AA = sb + KM_A, BB = sb + KM_B;

    for (int i = tid; i < 2 * B_ROWS * D_OUT; i += 512) s_s[i] = 0.f;

    float aL[8][4], aH[8][4];

    for (int mt = blockIdx.x; mt < N_MT; mt += gridDim.x) {
        __syncthreads();   // prior mt's last MMA done before B overwrite
        int mbase = mt * 128;
        // B tile: 128 hc rows (2048 x 16B over 512 threads)
#pragma unroll
        for (int i = 0; i < 4; i++) {
            int idx = tid + i * 512;
            int r = idx >> 4, kb = (idx & 15) * 16;
            *(uint4*)(smem + KM_B + r * 256 + (kb ^ ((r & 7) << 4))) =
                *(const uint4*)((const char*)g_hc + ((size_t)mbase + r) * 256 + kb);
        }
        if (tid < 128) {
            cn_s[tid]  = g_hcn2[mbase + tid];
            cls_s[tid] = g_cls[mbase + tid];
        }
        int c_lo = g_cls[mbase], c_hi = g_cls[mbase + 127];
        const float* cnp = cn_s + wc * 64 + (lane & 3) * 2;

#pragma unroll 1
        for (int sc = 0; sc < 4; sc++) {
            if (sc) __syncthreads();   // all warps done reading previous A
            // A: 256 query rows (4096 x 16B over 512 threads)
#pragma unroll
            for (int i = 0; i < 8; i++) {
                int idx = tid + i * 512;
                int r = idx >> 4, kb = (idx & 15) * 16;
                *(uint4*)(smem + KM_A + r * 256 + (kb ^ ((r & 7) << 4))) =
                    *(const uint4*)((const char*)g_h + ((size_t)sc * 256 + r) * 256 + kb);
            }
            __syncthreads();

            mma2(aL, aH, AA, BB, wr, wc, lane);

            int rbL = sc * 256 + wr * 16 + (lane >> 2);
            float hnL0 = g_hn2[rbL],       hnL1 = g_hn2[rbL + 8];
            float hnH0 = g_hn2[rbL + 128], hnH1 = g_hn2[rbL + 136];

            if (c_lo == c_hi) {
                float rsL[2] = {0.f, 0.f}, rsH[2] = {0.f, 0.f};
#pragma unroll
                for (int nt = 0; nt < 8; nt++) {
                    float c0 = cnp[nt * 8], c1 = cnp[nt * 8 + 1];
                    epi_slice(aL[nt], hnL0, hnL1, c0, c1, rsL);
                    epi_slice(aH[nt], hnH0, hnH1, c0, c1, rsH);
                }
                epi_reduce_store(rsL, s_s, sc * 256 + wr * 16,       c_lo, wc, lane);
                epi_reduce_store(rsH, s_s, sc * 256 + 128 + wr * 16, c_lo, wc, lane);
            } else {
                const int* clp = cls_s + wc * 64 + (lane & 3) * 2;
                exp_inplace(aL, hnL0, hnL1, cnp);
                exp_inplace(aH, hnH0, hnH1, cnp);
                for (int cc = c_lo; cc <= c_hi; cc++) {
                    float rsL[2] = {0.f, 0.f}, rsH[2] = {0.f, 0.f};
#pragma unroll
                    for (int nt = 0; nt < 8; nt++) {
                        int cl0 = clp[nt * 8], cl1 = clp[nt * 8 + 1];
                        rsL[0] += (cl0 == cc) ? aL[nt][0] : 0.f;
                        rsL[0] += (cl1 == cc) ? aL[nt][1] : 0.f;
                        rsL[1] += (cl0 == cc) ? aL[nt][2] : 0.f;
                        rsL[1] += (cl1 == cc) ? aL[nt][3] : 0.f;
                        rsH[0] += (cl0 == cc) ? aH[nt][0] : 0.f;
                        rsH[0] += (cl1 == cc) ? aH[nt][1] : 0.f;
                        rsH[1] += (cl0 == cc) ? aH[nt][2] : 0.f;
                        rsH[1] += (cl1 == cc) ? aH[nt][3] : 0.f;
                    }
                    epi_reduce_store(rsL, s_s, sc * 256 + wr * 16,       cc, wc, lane);
                    epi_reduce_store(rsH, s_s, sc * 256 + 128 + wr * 16, cc, wc, lane);
                }
            }
        }
    }
    __syncthreads();
    for (int i = tid; i < B_ROWS * D_OUT; i += 512)
        g_part[(size_t)blockIdx.x * (B_ROWS * D_OUT) + i] =
            s_s[i] + s_s[B_ROWS * D_OUT + i];
}

// ---------------------------------------------------------------- k_final
__global__ void k_final(float* __restrict__ out, int nctas) {
    __shared__ float red[320];
    int b = blockIdx.x, t = threadIdx.x;    // 320 threads
    int g = t / 10, c = t - g * 10;
    float s = 0.f;
    for (int p = g; p < nctas; p += 32)
        s += g_part[(size_t)p * (B_ROWS * D_OUT) + b * D_OUT + c];
    red[t] = s;
    __syncthreads();
    if (t < 160) red[t] += red[t + 160]; __syncthreads();
    if (t < 80)  red[t] += red[t + 80];  __syncthreads();
    if (t < 40)  red[t] += red[t + 40];  __syncthreads();
    if (t < 20)  red[t] += red[t + 20];  __syncthreads();
    if (t < 10)  red[t] += red[t + 10];
    __syncthreads();
    if (t < 10) {
        float tot = 0.f;
#pragma unroll
        for (int cc = 0; cc < 10; cc++) tot += red[cc];
        out[b * D_OUT + t] = logf(red[t] / tot + 1e-7f);
    }
}

// ---------------------------------------------------------------- launch
extern "C" void kernel_launch(void* const* d_in, const int* in_sizes, int n_in,
                              void* d_out, int out_size) {
    const float* x  = (const float*)d_in[0];
    const float* cx = (const float*)d_in[2];
    const int*   cy = (const int*)d_in[3];
    const float* W  = (const float*)d_in[4];
    const float* be = (const float*)d_in[5];
    float* out = (float*)d_out;

    int dev = 0;
    cudaGetDevice(&dev);
    int nsm = 148;
    cudaDeviceGetAttribute(&nsm, cudaDevAttrMultiProcessorCount, dev);
    if (nsm < 1 || nsm > MAX_CTAS) nsm = 148;

    cudaFuncSetAttribute(k_proj, cudaFuncAttributeMaxDynamicSharedMemorySize, SMEM_P_BYTES);
    cudaFuncSetAttribute(k_main, cudaFuncAttributeMaxDynamicSharedMemorySize, SMEM_MAIN_BYTES);

    k_hist<<<NBLK, 256>>>(cy);
    k_scan<<<1, 320>>>();
    k_rank<<<NBLK, 256>>>(cy);
    k_proj<<<N_PCT + 16, 256, SMEM_P_BYTES>>>(x, cx, W, be);
    k_main<<<nsm, 512, SMEM_MAIN_BYTES>>>();
    k_final<<<B_ROWS, 320>>>(out, nsm);
}

// round 10
// speedup vs baseline: 1.3838x; 1.0710x over previous
#include <cuda_runtime.h>
#include <cuda_fp16.h>
#include <math.h>
#include <stdint.h>

#define B_ROWS 1024
#define M_TOT  200000
#define D_INP  256
#define DIM    128
#define D_OUT  10
#define M_PAD  200192            /* 1564*128 */
#define N_MT   1564              /* k_main m-tiles of 128 */
#define N_T    1572              /* k_proj tiles: 8 query + 1564 candidate */
#define NBLK   782               /* histogram blocks of 256 */
#define MAX_CTAS 512

// ---------------------------------------------------------------- helpers
__device__ __forceinline__ uint32_t smem_to_u32(const void* p) {
    uint32_t a;
    asm("{ .reg .u64 t; cvta.to.shared.u64 t, %1; cvt.u32.u64 %0, t; }"
        : "=r"(a) : "l"(p));
    return a;
}
__device__ __forceinline__ void ldsm4(uint32_t r[4], uint32_t addr) {
    asm volatile("ldmatrix.sync.aligned.m8n8.x4.shared.b16 {%0,%1,%2,%3}, [%4];"
                 : "=r"(r[0]), "=r"(r[1]), "=r"(r[2]), "=r"(r[3]) : "r"(addr));
}
__device__ __forceinline__ void mma16816(float c[4], const uint32_t a[4],
                                         const uint32_t b0, const uint32_t b1) {
    asm volatile("mma.sync.aligned.m16n8k16.row.col.f32.f16.f16.f32 "
                 "{%0,%1,%2,%3}, {%4,%5,%6,%7}, {%8,%9}, {%0,%1,%2,%3};"
                 : "+f"(c[0]), "+f"(c[1]), "+f"(c[2]), "+f"(c[3])
                 : "r"(a[0]), "r"(a[1]), "r"(a[2]), "r"(a[3]), "r"(b0), "r"(b1));
}
__device__ __forceinline__ float sqrt_approx(float x) {
    float r; asm("sqrt.approx.f32 %0, %1;" : "=f"(r) : "f"(x)); return r;
}
// A-fragment ldmatrix (16 rows x 16 k)
__device__ __forceinline__ void lda_frag(uint32_t a[4], uint32_t base, int R0,
                                         int ks, int lane, int rstride) {
    int row = R0 + (lane & 15);
    int kb  = ks * 32 + ((lane >> 4) << 4);
    ldsm4(a, base + row * rstride + (kb ^ ((row & 7) << 4)));
}
// B-fragment ldmatrix: two n-tiles of 8
__device__ __forceinline__ void ldb_frag(uint32_t b[4], uint32_t base, int N0,
                                         int ks, int lane, int rstride) {
    int row = N0 + (lane & 7) + ((lane >> 4) << 3);
    int kb  = ks * 32 + ((lane >> 3) & 1) * 16;
    ldsm4(b, base + row * rstride + (kb ^ ((row & 7) << 4)));
}

// ---------------------------------------------------------------- scratch
__device__ __half g_h   [B_ROWS * DIM];
__device__ float  g_hn2 [B_ROWS];
__device__ __half g_hc  [(size_t)M_PAD * DIM];
__device__ float  g_hcn2[M_PAD];
__device__ int    g_src [M_PAD];
__device__ int    g_cls [M_PAD];
__device__ int    g_bh  [NBLK * D_OUT];
__device__ int    g_boff[NBLK * D_OUT];
__device__ int    g_coff[D_OUT];
__device__ float  g_part[(size_t)MAX_CTAS * B_ROWS * D_OUT];

// ---------------------------------------------------------------- sort
__global__ void k_hist(const int* __restrict__ cy) {
    __shared__ int cnt[D_OUT];
    int t = threadIdx.x, b = blockIdx.x;
    if (t < D_OUT) cnt[t] = 0;
    __syncthreads();
    int m = b * 256 + t;
    if (m < M_TOT) atomicAdd(&cnt[cy[m]], 1);
    __syncthreads();
    if (t < D_OUT) g_bh[b * D_OUT + t] = cnt[t];
}
__global__ void k_scan() {
    __shared__ int tot[D_OUT];
    int w = threadIdx.x >> 5, lane = threadIdx.x & 31;
    if (w < D_OUT) {
        int run = 0;
        for (int base = 0; base < NBLK; base += 32) {
            int b = base + lane;
            int v = (b < NBLK) ? g_bh[b * D_OUT + w] : 0;
            int s = v;
#pragma unroll
            for (int o = 1; o < 32; o <<= 1) {
                int t = __shfl_up_sync(0xFFFFFFFF, s, o);
                if (lane >= o) s += t;
            }
            if (b < NBLK) g_boff[b * D_OUT + w] = run + s - v;
            run += __shfl_sync(0xFFFFFFFF, s, 31);
        }
        if (lane == 0) tot[w] = run;
    }
    __syncthreads();
    if (threadIdx.x == 0) {
        int off = 0;
        for (int c = 0; c < D_OUT; c++) { g_coff[c] = off; off += tot[c]; }
    }
    for (int p = M_TOT + threadIdx.x; p < M_PAD; p += 320) g_cls[p] = D_OUT - 1;
}
__global__ void k_rank(const int* __restrict__ cy) {
    __shared__ int cls[256];
    int t = threadIdx.x, b = blockIdx.x;
    int m = b * 256 + t;
    int c = (m < M_TOT) ? cy[m] : -1;
    cls[t] = c;
    __syncthreads();
    if (m < M_TOT) {
        int r = 0;
        for (int j = 0; j < t; j++) r += (cls[j] == c);
        int pos = g_coff[c] + g_boff[b * D_OUT + c] + r;
        g_src[pos] = m;
        g_cls[pos] = c;
    }
}

// ---------------------------------------------------------------- k_proj (persistent)
// 148 CTAs x 512 threads. W converted to smem once; tiles of 128 rows strided
// across CTAs with double-buffered A (gather of next tile overlaps MMA).
#define PW     0          /* 128 x 512B = 64KB (fp16 W, swizzled) */
#define PA0    65536      /* 64KB */
#define PA1    131072     /* 64KB */
#define PBIAS  196608     /* 512B */
#define PSRC0  197120     /* 512B */
#define PSRC1  197632     /* 512B */
#define PPART  198144     /* 1KB */
#define SMEM_P_BYTES 199680

__device__ __forceinline__ void proj_gather(char* smem, int abuf_off,
                                            const float* __restrict__ mat,
                                            const int* srcs, int tid) {
#pragma unroll
    for (int i = 0; i < 8; i++) {
        int idx = tid + i * 512;
        int r = idx >> 5, kb = (idx & 31) * 16;
        const float4* s4 = (const float4*)(mat + (size_t)srcs[r] * D_INP + kb / 2);
        float4 v0 = s4[0], v1 = s4[1];
        __half2 h0 = __floats2half2_rn(v0.x, v0.y), h1 = __floats2half2_rn(v0.z, v0.w);
        __half2 h2 = __floats2half2_rn(v1.x, v1.y), h3 = __floats2half2_rn(v1.z, v1.w);
        *(uint4*)(smem + abuf_off + r * 512 + (kb ^ ((r & 7) << 4))) =
            make_uint4(*(uint32_t*)&h0, *(uint32_t*)&h1, *(uint32_t*)&h2, *(uint32_t*)&h3);
    }
}

__global__ __launch_bounds__(512, 1) void k_proj(const float* __restrict__ x,
                                                 const float* __restrict__ cx,
                                                 const float* __restrict__ W,
                                                 const float* __restrict__ be) {
    extern __shared__ char smem[];
    uint32_t sb = smem_to_u32(smem);
    float* bias_s = (float*)(smem + PBIAS);
    float* part   = (float*)(smem + PPART);
    int* srcs_b[2] = {(int*)(smem + PSRC0), (int*)(smem + PSRC1)};
    uint32_t abuf[2] = {sb + PA0, sb + PA1};
    int aoff[2] = {PA0, PA1};
    int tid = threadIdx.x, lane = tid & 31, wid = tid >> 5;
    int wr = wid & 7, wc = wid >> 3;

    // W -> smem fp16 (once)
#pragma unroll
    for (int i = 0; i < 8; i++) {
        int idx = tid + i * 512;
        int r = idx >> 5, kb = (idx & 31) * 16;
        const float4* s4 = (const float4*)(W + (size_t)r * D_INP + kb / 2);
        float4 v0 = s4[0], v1 = s4[1];
        __half2 h0 = __floats2half2_rn(v0.x, v0.y), h1 = __floats2half2_rn(v0.z, v0.w);
        __half2 h2 = __floats2half2_rn(v1.x, v1.y), h3 = __floats2half2_rn(v1.z, v1.w);
        *(uint4*)(smem + PW + r * 512 + (kb ^ ((r & 7) << 4))) =
            make_uint4(*(uint32_t*)&h0, *(uint32_t*)&h1, *(uint32_t*)&h2, *(uint32_t*)&h3);
    }
    if (tid < 128) bias_s[tid] = be[tid];

    int stride = gridDim.x;
    int t0 = blockIdx.x;
    // preload srcs + gather for first tile
    if (t0 < N_T && tid < 128) {
        bool isq = t0 < 8;
        int p = isq ? (t0 * 128 + tid) : ((t0 - 8) * 128 + tid);
        srcs_b[0][tid] = isq ? p : ((p < M_TOT) ? g_src[p] : 0);
    }
    __syncthreads();
    if (t0 < N_T)
        proj_gather(smem, aoff[0], (t0 < 8) ? x : cx, srcs_b[0], tid);

    int par = 0;
    for (int t = t0; t < N_T; t += stride) {
        bool isq = t < 8;
        int tile = isq ? t : t - 8;
        int tn = t + stride;
        // stage srcs for next tile
        if (tn < N_T && tid < 128) {
            bool isqn = tn < 8;
            int p = isqn ? (tn * 128 + tid) : ((tn - 8) * 128 + tid);
            srcs_b[par ^ 1][tid] = isqn ? p : ((p < M_TOT) ? g_src[p] : 0);
        }
        __syncthreads();   // A[par] STS visible; srcs[par^1] visible
        if (tn < N_T)
            proj_gather(smem, aoff[par ^ 1], (tn < 8) ? x : cx, srcs_b[par ^ 1], tid);

        // MMA: A[par] (128x256) x W (128x256)^T
        float acc[8][4];
#pragma unroll
        for (int n = 0; n < 8; n++)
#pragma unroll
            for (int j = 0; j < 4; j++) acc[n][j] = 0.f;
#pragma unroll
        for (int ks = 0; ks < 16; ks++) {
            uint32_t a[4], bf[4][4];
            lda_frag(a, abuf[par], wr * 16, ks, lane, 512);
#pragma unroll
            for (int p = 0; p < 4; p++)
                ldb_frag(bf[p], sb + PW, wc * 64 + p * 16, ks, lane, 512);
#pragma unroll
            for (int nt = 0; nt < 8; nt++)
                mma16816(acc[nt], a, bf[nt >> 1][(nt & 1) * 2], bf[nt >> 1][(nt & 1) * 2 + 1]);
        }

        // epilogue
        __half* out_h  = isq ? g_h   : g_hc;
        float*  out_n2 = isq ? g_hn2 : g_hcn2;
        float sumsq[2] = {0.f, 0.f};
#pragma unroll
        for (int hr = 0; hr < 2; hr++) {
            int row = wr * 16 + (lane >> 2) + hr * 8;
            size_t gm = (size_t)tile * 128 + row;
#pragma unroll
            for (int nt = 0; nt < 8; nt++) {
                int d0 = wc * 64 + nt * 8 + (lane & 3) * 2;
                float v0 = acc[nt][hr * 2 + 0] + bias_s[d0];
                float v1 = acc[nt][hr * 2 + 1] + bias_s[d0 + 1];
                __half2 hp = __floats2half2_rn(v0, v1);
                float2 vr = __half22float2(hp);
                sumsq[hr] = fmaf(vr.x, vr.x, sumsq[hr]);
                sumsq[hr] = fmaf(vr.y, vr.y, sumsq[hr]);
                *(__half2*)(out_h + gm * DIM + d0) = hp;
            }
        }
#pragma unroll
        for (int hr = 0; hr < 2; hr++) {
            float v = sumsq[hr];
            v += __shfl_xor_sync(0xFFFFFFFF, v, 1);
            v += __shfl_xor_sync(0xFFFFFFFF, v, 2);
            if ((lane & 3) == 0) {
                int row = wr * 16 + (lane >> 2) + hr * 8;
                part[row * 2 + wc] = v;
            }
        }
        __syncthreads();
        if (tid < 128) {
            size_t gm = (size_t)tile * 128 + tid;
            float v = part[tid * 2] + part[tid * 2 + 1];
            out_n2[gm] = (isq || gm < M_TOT) ? v : 3e38f;
        }
        par ^= 1;
    }
}

// ---------------------------------------------------------------- k_main
// 512 threads / 16 warps: wr=wid&7 (16-row strip), wc=wid>>3 (64-col half)
// unit = 128-candidate tile; per step 256 queries (two accumulator sets)
#define KM_A   0        /* 256 rows x 256B = 64KB */
#define KM_B   65536    /* 128 rows x 256B = 32KB */
#define KM_CN  98304    /* 128 f32 */
#define KM_CLS 98816    /* 128 i32 */
#define KM_SS  99328    /* 2 x 1024 x 10 f32 = 80KB */
#define SMEM_MAIN_BYTES (KM_SS + 2 * B_ROWS * D_OUT * 4)

__device__ __forceinline__ void epi_reduce_store(float (&rs)[2], float* s_s,
                                                 int brow_base, int cls,
                                                 int wc, int lane) {
#pragma unroll
    for (int hr = 0; hr < 2; hr++) {
        float v = rs[hr];
        v += __shfl_xor_sync(0xFFFFFFFF, v, 1);
        v += __shfl_xor_sync(0xFFFFFFFF, v, 2);
        if ((lane & 3) == 0) {
            int brow = brow_base + (lane >> 2) + hr * 8;
            s_s[wc * (B_ROWS * D_OUT) + brow * D_OUT + cls] += v;
        }
    }
}

__device__ __forceinline__ void epi_slice(const float accP[4], float hn0, float hn1,
                                          float c0, float c1, float (&rs)[2]) {
    float sq0 = fmaxf(fmaf(-2.f, accP[0], hn0 + c0), 1e-30f);
    float sq1 = fmaxf(fmaf(-2.f, accP[1], hn0 + c1), 1e-30f);
    float sq2 = fmaxf(fmaf(-2.f, accP[2], hn1 + c0), 1e-30f);
    float sq3 = fmaxf(fmaf(-2.f, accP[3], hn1 + c1), 1e-30f);
    rs[0] += __expf(-sqrt_approx(sq0)) + __expf(-sqrt_approx(sq1));
    rs[1] += __expf(-sqrt_approx(sq2)) + __expf(-sqrt_approx(sq3));
}

// dual MMA: 256 A-rows (lo strip wr*16, hi strip 128+wr*16), shared ldb
__device__ __forceinline__ void mma2(float (&aL)[8][4], float (&aH)[8][4],
                                     uint32_t A, uint32_t B,
                                     int wr, int wc, int lane) {
#pragma unroll
    for (int n = 0; n < 8; n++)
#pragma unroll
        for (int j = 0; j < 4; j++) { aL[n][j] = 0.f; aH[n][j] = 0.f; }
#pragma unroll
    for (int ks = 0; ks < 8; ks++) {
        uint32_t alo[4], ahi[4], bf[4][4];
        lda_frag(alo, A, wr * 16,       ks, lane, 256);
        lda_frag(ahi, A, 128 + wr * 16, ks, lane, 256);
#pragma unroll
        for (int p = 0; p < 4; p++)
            ldb_frag(bf[p], B, wc * 64 + p * 16, ks, lane, 256);
#pragma unroll
        for (int nt = 0; nt < 8; nt++) {
            mma16816(aL[nt], alo, bf[nt >> 1][(nt & 1) * 2], bf[nt >> 1][(nt & 1) * 2 + 1]);
            mma16816(aH[nt], ahi, bf[nt >> 1][(nt & 1) * 2], bf[nt >> 1][(nt & 1) * 2 + 1]);
        }
    }
}

__device__ __forceinline__ void exp_inplace(float (&a)[8][4], float hn0, float hn1,
                                            const float* cnp) {
#pragma unroll
    for (int nt = 0; nt < 8; nt++) {
        float c0 = cnp[nt * 8], c1 = cnp[nt * 8 + 1];
        float sq0 = fmaxf(fmaf(-2.f, a[nt][0], hn0 + c0), 1e-30f);
        float sq1 = fmaxf(fmaf(-2.f, a[nt][1], hn0 + c1), 1e-30f);
        float sq2 = fmaxf(fmaf(-2.f, a[nt][2], hn1 + c0), 1e-30f);
        float sq3 = fmaxf(fmaf(-2.f, a[nt][3], hn1 + c1), 1e-30f);
        a[nt][0] = __expf(-sqrt_approx(sq0));
        a[nt][1] = __expf(-sqrt_approx(sq1));
        a[nt][2] = __expf(-sqrt_approx(sq2));
        a[nt][3] = __expf(-sqrt_approx(sq3));
    }
}

__global__ __launch_bounds__(512, 1) void k_main() {
    extern __shared__ char smem[];
    uint32_t sb = smem_to_u32(smem);
    float* s_s   = (float*)(smem + KM_SS);
    float* cn_s  = (float*)(smem + KM_CN);
    int*   cls_s = (int*)(smem + KM_CLS);
    int tid = threadIdx.x, lane = tid & 31, wid = tid >> 5;
    int wr = wid & 7, wc = wid >> 3;
    uint32_t AA = sb + KM_A, BB = sb + KM_B;

    for (int i = tid; i < 2 * B_ROWS * D_OUT; i += 512) s_s[i] = 0.f;

    float aL[8][4], aH[8][4];

    for (int mt = blockIdx.x; mt < N_MT; mt += gridDim.x) {
        __syncthreads();
        int mbase = mt * 128;
#pragma unroll
        for (int i = 0; i < 4; i++) {
            int idx = tid + i * 512;
            int r = idx >> 4, kb = (idx & 15) * 16;
            *(uint4*)(smem + KM_B + r * 256 + (kb ^ ((r & 7) << 4))) =
                *(const uint4*)((const char*)g_hc + ((size_t)mbase + r) * 256 + kb);
        }
        if (tid < 128) {
            cn_s[tid]  = g_hcn2[mbase + tid];
            cls_s[tid] = g_cls[mbase + tid];
        }
        int c_lo = g_cls[mbase], c_hi = g_cls[mbase + 127];
        const float* cnp = cn_s + wc * 64 + (lane & 3) * 2;

#pragma unroll 1
        for (int sc = 0; sc < 4; sc++) {
            if (sc) __syncthreads();
#pragma unroll
            for (int i = 0; i < 8; i++) {
                int idx = tid + i * 512;
                int r = idx >> 4, kb = (idx & 15) * 16;
                *(uint4*)(smem + KM_A + r * 256 + (kb ^ ((r & 7) << 4))) =
                    *(const uint4*)((const char*)g_h + ((size_t)sc * 256 + r) * 256 + kb);
            }
            __syncthreads();

            mma2(aL, aH, AA, BB, wr, wc, lane);

            int rbL = sc * 256 + wr * 16 + (lane >> 2);
            float hnL0 = g_hn2[rbL],       hnL1 = g_hn2[rbL + 8];
            float hnH0 = g_hn2[rbL + 128], hnH1 = g_hn2[rbL + 136];

            if (c_lo == c_hi) {
                float rsL[2] = {0.f, 0.f}, rsH[2] = {0.f, 0.f};
#pragma unroll
                for (int nt = 0; nt < 8; nt++) {
                    float c0 = cnp[nt * 8], c1 = cnp[nt * 8 + 1];
                    epi_slice(aL[nt], hnL0, hnL1, c0, c1, rsL);
                    epi_slice(aH[nt], hnH0, hnH1, c0, c1, rsH);
                }
                epi_reduce_store(rsL, s_s, sc * 256 + wr * 16,       c_lo, wc, lane);
                epi_reduce_store(rsH, s_s, sc * 256 + 128 + wr * 16, c_lo, wc, lane);
            } else {
                const int* clp = cls_s + wc * 64 + (lane & 3) * 2;
                exp_inplace(aL, hnL0, hnL1, cnp);
                exp_inplace(aH, hnH0, hnH1, cnp);
                for (int cc = c_lo; cc <= c_hi; cc++) {
                    float rsL[2] = {0.f, 0.f}, rsH[2] = {0.f, 0.f};
#pragma unroll
                    for (int nt = 0; nt < 8; nt++) {
                        int cl0 = clp[nt * 8], cl1 = clp[nt * 8 + 1];
                        rsL[0] += (cl0 == cc) ? aL[nt][0] : 0.f;
                        rsL[0] += (cl1 == cc) ? aL[nt][1] : 0.f;
                        rsL[1] += (cl0 == cc) ? aL[nt][2] : 0.f;
                        rsL[1] += (cl1 == cc) ? aL[nt][3] : 0.f;
                        rsH[0] += (cl0 == cc) ? aH[nt][0] : 0.f;
                        rsH[0] += (cl1 == cc) ? aH[nt][1] : 0.f;
                        rsH[1] += (cl0 == cc) ? aH[nt][2] : 0.f;
                        rsH[1] += (cl1 == cc) ? aH[nt][3] : 0.f;
                    }
                    epi_reduce_store(rsL, s_s, sc * 256 + wr * 16,       cc, wc, lane);
                    epi_reduce_store(rsH, s_s, sc * 256 + 128 + wr * 16, cc, wc, lane);
                }
            }
        }
    }
    __syncthreads();
    for (int i = tid; i < B_ROWS * D_OUT; i += 512)
        g_part[(size_t)blockIdx.x * (B_ROWS * D_OUT) + i] =
            s_s[i] + s_s[B_ROWS * D_OUT + i];
}

// ---------------------------------------------------------------- k_final
__global__ void k_final(float* __restrict__ out, int nctas) {
    __shared__ float red[320];
    int b = blockIdx.x, t = threadIdx.x;    // 320 threads
    int g = t / 10, c = t - g * 10;
    float s = 0.f;
    for (int p = g; p < nctas; p += 32)
        s += g_part[(size_t)p * (B_ROWS * D_OUT) + b * D_OUT + c];
    red[t] = s;
    __syncthreads();
    if (t < 160) red[t] += red[t + 160]; __syncthreads();
    if (t < 80)  red[t] += red[t + 80];  __syncthreads();
    if (t < 40)  red[t] += red[t + 40];  __syncthreads();
    if (t < 20)  red[t] += red[t + 20];  __syncthreads();
    if (t < 10)  red[t] += red[t + 10];
    __syncthreads();
    if (t < 10) {
        float tot = 0.f;
#pragma unroll
        for (int cc = 0; cc < 10; cc++) tot += red[cc];
        out[b * D_OUT + t] = logf(red[t] / tot + 1e-7f);
    }
}

// ---------------------------------------------------------------- launch
extern "C" void kernel_launch(void* const* d_in, const int* in_sizes, int n_in,
                              void* d_out, int out_size) {
    const float* x  = (const float*)d_in[0];
    const float* cx = (const float*)d_in[2];
    const int*   cy = (const int*)d_in[3];
    const float* W  = (const float*)d_in[4];
    const float* be = (const float*)d_in[5];
    float* out = (float*)d_out;

    int dev = 0;
    cudaGetDevice(&dev);
    int nsm = 148;
    cudaDeviceGetAttribute(&nsm, cudaDevAttrMultiProcessorCount, dev);
    if (nsm < 1 || nsm > MAX_CTAS) nsm = 148;

    cudaFuncSetAttribute(k_proj, cudaFuncAttributeMaxDynamicSharedMemorySize, SMEM_P_BYTES);
    cudaFuncSetAttribute(k_main, cudaFuncAttributeMaxDynamicSharedMemorySize, SMEM_MAIN_BYTES);

    k_hist<<<NBLK, 256>>>(cy);
    k_scan<<<1, 320>>>();
    k_rank<<<NBLK, 256>>>(cy);
    k_proj<<<nsm, 512, SMEM_P_BYTES>>>(x, cx, W, be);
    k_main<<<nsm, 512, SMEM_MAIN_BYTES>>>();
    k_final<<<B_ROWS, 320>>>(out, nsm);
}